// round 1
// baseline (speedup 1.0000x reference)
#include <cuda_runtime.h>
#include <cuda_bf16.h>
#include <math.h>

// Problem constants (from reference):
//   PER_LOC_BIN_NUM = 12, NUM_HEAD_BIN = 12
//   C = 12*4 + 1 + 12*2 + 3 = 76
//   out cols = 7
#define PER        12
#define NHEAD      12
#define NCOL       76
#define ROWS       128         // rows per block == threads per block
#define PSTRIDE    77          // padded smem row stride (bank-conflict free)

__global__ __launch_bounds__(ROWS)
void rpn_decode_kernel(const float* __restrict__ roi,
                       const float* __restrict__ pred,
                       const float* __restrict__ anchor,
                       float* __restrict__ out,
                       int N)
{
    __shared__ float pred_s[ROWS * PSTRIDE];   // 39424 B
    __shared__ float roi_s [ROWS * 7];         //  3584 B
    __shared__ float out_s [ROWS * 7];         //  3584 B

    const int tid  = threadIdx.x;
    const int row0 = blockIdx.x * ROWS;
    const int rows = min(ROWS, N - row0);

    // ---- Stage pred_reg rows into smem, fully coalesced ----
    const float* pbase = pred + (size_t)row0 * NCOL;
    if (rows == ROWS) {
        // block base byte offset = row0*304, row0 multiple of 128 -> 16B aligned
        const float4* p4 = reinterpret_cast<const float4*>(pbase);
        const int n4 = (ROWS * NCOL) / 4;      // 2432
        for (int i = tid; i < n4; i += ROWS) {
            float4 v = p4[i];
            int e = i * 4;
            int r = e / NCOL;
            int c = e - r * NCOL;
            float vv[4] = {v.x, v.y, v.z, v.w};
            #pragma unroll
            for (int k = 0; k < 4; k++) {
                int cc = c + k, rr = r;
                if (cc >= NCOL) { cc -= NCOL; rr++; }   // crosses one row at most
                pred_s[rr * PSTRIDE + cc] = vv[k];
            }
        }
    } else {
        const int nelem = rows * NCOL;
        for (int i = tid; i < nelem; i += ROWS) {
            int r = i / NCOL;
            int c = i - r * NCOL;
            pred_s[r * PSTRIDE + c] = pbase[i];
        }
    }

    // ---- Stage roi rows (7 floats each), coalesced ----
    const float* rbase = roi + (size_t)row0 * 7;
    for (int i = tid; i < rows * 7; i += ROWS)
        roi_s[i] = rbase[i];

    __syncthreads();

    // ---- Per-row decode (one thread per row) ----
    if (tid < rows) {
        const float* p = pred_s + tid * PSTRIDE;

        // argmax over x bins [0,12)  (first max wins: strict >)
        int xb = 0; float xm = p[0];
        #pragma unroll
        for (int i = 1; i < PER; i++) { float v = p[i]; if (v > xm) { xm = v; xb = i; } }
        // argmax over z bins [12,24)
        int zb = 0; float zm = p[PER];
        #pragma unroll
        for (int i = 1; i < PER; i++) { float v = p[PER + i]; if (v > zm) { zm = v; zb = i; } }

        const float LOC_BIN = 0.5f;
        float pos_x = (float)xb * LOC_BIN + 0.25f - 3.0f + p[2 * PER + xb] * LOC_BIN;
        float pos_z = (float)zb * LOC_BIN + 0.25f - 3.0f + p[3 * PER + zb] * LOC_BIN;

        // start = 48: y offset
        float pos_y = roi_s[tid * 7 + 1] + p[4 * PER];

        // heading bins [49, 61), residuals [61, 73)
        int rb = 0; float rm = p[4 * PER + 1];
        #pragma unroll
        for (int i = 1; i < NHEAD; i++) {
            float v = p[4 * PER + 1 + i];
            if (v > rm) { rm = v; rb = i; }
        }
        float ry_res = p[4 * PER + 1 + NHEAD + rb];

        const float TWO_PI = 6.2831853071795864769f;
        const float PI_F   = 3.1415926535897932385f;
        const float APC    = TWO_PI / (float)NHEAD;   // angle per class
        float ry = (float)rb * APC + ry_res * (APC * 0.5f);
        ry = fmodf(ry, TWO_PI);
        if (ry < 0.0f) ry += TWO_PI;                  // floor-mod like jnp %
        if (ry > PI_F) ry -= TWO_PI;

        // hwl = pred * anchor + anchor
        float a0 = __ldg(anchor + 0);
        float a1 = __ldg(anchor + 1);
        float a2 = __ldg(anchor + 2);
        float h = fmaf(p[73], a0, a0);
        float w = fmaf(p[74], a1, a1);
        float l = fmaf(p[75], a2, a2);

        float roi_ry = roi_s[tid * 7 + 6];
        float s, c;
        sincosf(roi_ry, &s, &c);      // cos(-x)=c, sin(-x)=-s
        float cn = c, sn = -s;

        float x_rot = pos_x * cn - pos_z * sn;
        float z_rot = pos_x * sn + pos_z * cn;

        out_s[tid * 7 + 0] = x_rot + roi_s[tid * 7 + 0];
        out_s[tid * 7 + 1] = pos_y;
        out_s[tid * 7 + 2] = z_rot + roi_s[tid * 7 + 2];
        out_s[tid * 7 + 3] = h;
        out_s[tid * 7 + 4] = w;
        out_s[tid * 7 + 5] = l;
        out_s[tid * 7 + 6] = ry + roi_ry;
    }

    __syncthreads();

    // ---- Coalesced store of output tile ----
    float* obase = out + (size_t)row0 * 7;
    for (int i = tid; i < rows * 7; i += ROWS)
        obase[i] = out_s[i];
}

extern "C" void kernel_launch(void* const* d_in, const int* in_sizes, int n_in,
                              void* d_out, int out_size)
{
    const float* roi    = (const float*)d_in[0];   // (N,7)
    const float* pred   = (const float*)d_in[1];   // (N,76)
    const float* anchor = (const float*)d_in[2];   // (3,)
    float* out = (float*)d_out;                    // (N,7)

    int N = in_sizes[0] / 7;
    int blocks = (N + ROWS - 1) / ROWS;
    rpn_decode_kernel<<<blocks, ROWS>>>(roi, pred, anchor, out, N);
}

// round 2
// speedup vs baseline: 1.5927x; 1.5927x over previous
#include <cuda_runtime.h>
#include <cuda_bf16.h>
#include <math.h>

// RPN bbox decode: N rows, pred_reg row = 76 floats (19 aligned float4),
// roi row = 7 floats, out row = 7 floats.
#define PER    12
#define NHEAD  12
#define NCOL   76
#define TPB    256

__global__ __launch_bounds__(TPB)
void rpn_decode_kernel(const float* __restrict__ roi,
                       const float* __restrict__ pred,
                       const float* __restrict__ anchor,
                       float* __restrict__ out,
                       int N)
{
    const int row = blockIdx.x * TPB + threadIdx.x;
    if (row >= N) return;

    // ---- 19 independent aligned LDG.128 per thread (row*304B is 16B aligned) ----
    const float4* p4 = reinterpret_cast<const float4*>(pred + (size_t)row * NCOL);
    float4 v[19];
    #pragma unroll
    for (int i = 0; i < 19; i++) v[i] = __ldg(p4 + i);

    // roi fields we need: 0 (x), 1 (y), 2 (z), 6 (ry)
    const float* rp = roi + (size_t)row * 7;
    float roi_x  = __ldg(rp + 0);
    float roi_y  = __ldg(rp + 1);
    float roi_z  = __ldg(rp + 2);
    float roi_ry = __ldg(rp + 6);

    float a0 = __ldg(anchor + 0);
    float a1 = __ldg(anchor + 1);
    float a2 = __ldg(anchor + 2);

    // Unpack to a constant-indexed array (fully unrolled -> stays in registers)
    float xs[76];
    #pragma unroll
    for (int i = 0; i < 19; i++) {
        xs[4*i + 0] = v[i].x;
        xs[4*i + 1] = v[i].y;
        xs[4*i + 2] = v[i].z;
        xs[4*i + 3] = v[i].w;
    }

    // ---- Fused argmax + residual gather (all indices compile-time) ----
    // x: bins xs[0..11], residuals xs[24..35]
    int   xb = 0; float xm = xs[0]; float xres = xs[24];
    #pragma unroll
    for (int i = 1; i < PER; i++) {
        float b = xs[i];
        if (b > xm) { xm = b; xb = i; xres = xs[24 + i]; }
    }
    // z: bins xs[12..23], residuals xs[36..47]
    int   zb = 0; float zm = xs[12]; float zres = xs[36];
    #pragma unroll
    for (int i = 1; i < PER; i++) {
        float b = xs[12 + i];
        if (b > zm) { zm = b; zb = i; zres = xs[36 + i]; }
    }
    // heading: bins xs[49..60], residuals xs[61..72]
    int   rb = 0; float rm = xs[49]; float rres = xs[61];
    #pragma unroll
    for (int i = 1; i < NHEAD; i++) {
        float b = xs[49 + i];
        if (b > rm) { rm = b; rb = i; rres = xs[61 + i]; }
    }

    const float LOC_BIN = 0.5f;
    float pos_x = (float)xb * LOC_BIN + 0.25f - 3.0f + xres * LOC_BIN;
    float pos_z = (float)zb * LOC_BIN + 0.25f - 3.0f + zres * LOC_BIN;
    float pos_y = roi_y + xs[48];

    const float TWO_PI = 6.2831853071795864769f;
    const float PI_F   = 3.1415926535897932385f;
    const float APC    = TWO_PI / (float)NHEAD;
    float ry = (float)rb * APC + rres * (APC * 0.5f);
    ry = fmodf(ry, TWO_PI);
    if (ry < 0.0f) ry += TWO_PI;      // jnp floor-mod semantics
    if (ry > PI_F) ry -= TWO_PI;

    float h = fmaf(xs[73], a0, a0);
    float w = fmaf(xs[74], a1, a1);
    float l = fmaf(xs[75], a2, a2);

    float s, c;
    sincosf(roi_ry, &s, &c);          // cos(-x)=c, sin(-x)=-s
    float cn = c, sn = -s;

    float x_rot = pos_x * cn - pos_z * sn;
    float z_rot = pos_x * sn + pos_z * cn;

    float* o = out + (size_t)row * 7;
    o[0] = x_rot + roi_x;
    o[1] = pos_y;
    o[2] = z_rot + roi_z;
    o[3] = h;
    o[4] = w;
    o[5] = l;
    o[6] = ry + roi_ry;
}

extern "C" void kernel_launch(void* const* d_in, const int* in_sizes, int n_in,
                              void* d_out, int out_size)
{
    const float* roi    = (const float*)d_in[0];   // (N,7)
    const float* pred   = (const float*)d_in[1];   // (N,76)
    const float* anchor = (const float*)d_in[2];   // (3,)
    float* out = (float*)d_out;                    // (N,7)

    int N = in_sizes[0] / 7;
    int blocks = (N + TPB - 1) / TPB;
    rpn_decode_kernel<<<blocks, TPB>>>(roi, pred, anchor, out, N);
}

// round 3
// speedup vs baseline: 2.9726x; 1.8664x over previous
#include <cuda_runtime.h>
#include <cuda_bf16.h>
#include <math.h>

#define PER    12
#define NHEAD  12
#define NCOL   76          // floats per pred row = 19 float4 exactly
#define TILE   128         // rows per CTA
#define TPB    128

__device__ __forceinline__ unsigned smem_u32(const void* p) {
    return (unsigned)__cvta_generic_to_shared(p);
}
__device__ __forceinline__ void cpa16(unsigned dst, const void* src) {
    asm volatile("cp.async.cg.shared.global [%0], [%1], 16;" :: "r"(dst), "l"(src));
}
__device__ __forceinline__ void cpa4(unsigned dst, const void* src) {
    asm volatile("cp.async.ca.shared.global [%0], [%1], 4;" :: "r"(dst), "l"(src));
}

__global__ __launch_bounds__(TPB)
void rpn_decode_kernel(const float* __restrict__ roi,
                       const float* __restrict__ pred,
                       const float* __restrict__ anchor,
                       float* __restrict__ out,
                       int N)
{
    __shared__ float pred_s[TILE * NCOL];   // 38912 B, unpadded (copy == identity)
    __shared__ float roi_s [TILE * 7];      //  3584 B

    const int tid  = threadIdx.x;
    const int row0 = blockIdx.x * TILE;
    const int rows = min(TILE, N - row0);

    // ---- Stage-in via cp.async: contiguous, coalesced, fire-and-forget ----
    const char* psrc = (const char*)(pred + (size_t)row0 * NCOL);
    const unsigned sp = smem_u32(pred_s);
    if (rows == TILE) {
        #pragma unroll
        for (int i = 0; i < 19; i++) {
            int idx = tid + i * TPB;                   // float4 index in tile
            cpa16(sp + idx * 16, psrc + idx * 16);
        }
        const char* rsrc = (const char*)(roi + (size_t)row0 * 7);
        const unsigned sr = smem_u32(roi_s);
        #pragma unroll
        for (int i = 0; i < 2; i++) {
            int idx = tid + i * TPB;                   // float4 index, 224 total
            if (idx < (TILE * 7) / 4)
                cpa16(sr + idx * 16, rsrc + idx * 16);
        }
    } else {
        const int n4 = rows * 19;
        for (int i = tid; i < n4; i += TPB)
            cpa16(sp + i * 16, psrc + i * 16);
        const char* rsrc = (const char*)(roi + (size_t)row0 * 7);
        const unsigned sr = smem_u32(roi_s);
        for (int i = tid; i < rows * 7; i += TPB)
            cpa4(sr + i * 4, rsrc + i * 4);
    }
    asm volatile("cp.async.commit_group;" ::: "memory");

    float a0 = __ldg(anchor + 0);
    float a1 = __ldg(anchor + 1);
    float a2 = __ldg(anchor + 2);

    asm volatile("cp.async.wait_group 0;" ::: "memory");
    __syncthreads();

    // ---- Per-row decode (thread tid owns row tid) ----
    if (tid < rows) {
        const float* p = pred_s + tid * NCOL;

        // fused argmax + residual gather, first-max (strict >) semantics
        int   xb = 0; float xm = p[0];  float xres = p[24];
        #pragma unroll
        for (int i = 1; i < PER; i++) {
            float b = p[i];
            if (b > xm) { xm = b; xb = i; xres = p[24 + i]; }
        }
        int   zb = 0; float zm = p[12]; float zres = p[36];
        #pragma unroll
        for (int i = 1; i < PER; i++) {
            float b = p[12 + i];
            if (b > zm) { zm = b; zb = i; zres = p[36 + i]; }
        }
        int   rb = 0; float rm = p[49]; float rres = p[61];
        #pragma unroll
        for (int i = 1; i < NHEAD; i++) {
            float b = p[49 + i];
            if (b > rm) { rm = b; rb = i; rres = p[61 + i]; }
        }

        float y_off = p[48];
        float ph = p[73], pw = p[74], pl = p[75];

        float roi_x  = roi_s[tid * 7 + 0];
        float roi_y  = roi_s[tid * 7 + 1];
        float roi_z  = roi_s[tid * 7 + 2];
        float roi_ry = roi_s[tid * 7 + 6];

        const float LOC_BIN = 0.5f;
        float pos_x = (float)xb * LOC_BIN + 0.25f - 3.0f + xres * LOC_BIN;
        float pos_z = (float)zb * LOC_BIN + 0.25f - 3.0f + zres * LOC_BIN;
        float pos_y = roi_y + y_off;

        const float TWO_PI = 6.2831853071795864769f;
        const float PI_F   = 3.1415926535897932385f;
        const float APC    = TWO_PI / (float)NHEAD;
        float ry = (float)rb * APC + rres * (APC * 0.5f);
        ry = fmodf(ry, TWO_PI);
        if (ry < 0.0f) ry += TWO_PI;   // jnp floor-mod
        if (ry > PI_F) ry -= TWO_PI;

        float h = fmaf(ph, a0, a0);
        float w = fmaf(pw, a1, a1);
        float l = fmaf(pl, a2, a2);

        float s, c;
        sincosf(roi_ry, &s, &c);       // cos(-x)=c, sin(-x)=-s
        float cn = c, sn = -s;
        float x_rot = pos_x * cn - pos_z * sn;
        float z_rot = pos_x * sn + pos_z * cn;

        // stage output in place (thread owns this row; all reads already done)
        float* o = pred_s + tid * NCOL;
        o[0] = x_rot + roi_x;
        o[1] = pos_y;
        o[2] = z_rot + roi_z;
        o[3] = h;
        o[4] = w;
        o[5] = l;
        o[6] = ry + roi_ry;
    }

    __syncthreads();

    // ---- Coalesced stage-out ----
    float* obase = out + (size_t)row0 * 7;
    const int nout = rows * 7;
    #pragma unroll
    for (int k = 0; k < 7; k++) {
        int j = k * TPB + tid;
        if (j < nout) {
            int r = j / 7;
            int c = j - r * 7;
            obase[j] = pred_s[r * NCOL + c];
        }
    }
}

extern "C" void kernel_launch(void* const* d_in, const int* in_sizes, int n_in,
                              void* d_out, int out_size)
{
    const float* roi    = (const float*)d_in[0];   // (N,7)
    const float* pred   = (const float*)d_in[1];   // (N,76)
    const float* anchor = (const float*)d_in[2];   // (3,)
    float* out = (float*)d_out;                    // (N,7)

    int N = in_sizes[0] / 7;
    int blocks = (N + TILE - 1) / TILE;
    rpn_decode_kernel<<<blocks, TPB>>>(roi, pred, anchor, out, N);
}